// round 3
// baseline (speedup 1.0000x reference)
#include <cuda_runtime.h>
#include <mma.h>
#include <cstdint>
#include <cstddef>

using namespace nvcuda;

#define Bb 32
#define Ss 2048
#define Ii 256
#define Hh 256
#define G4 1024   // 4*H

// 256 MB scratch for the x-projection (device global: the sanctioned no-alloc path)
__device__ __align__(16) float g_P[(size_t)Bb * Ss * G4];

// ---------------- helpers ----------------
__device__ __forceinline__ void ffma2(unsigned long long &d, unsigned long long a, unsigned long long b) {
    asm volatile("fma.rn.f32x2 %0, %1, %2, %0;" : "+l"(d) : "l"(a), "l"(b));
}
__device__ __forceinline__ unsigned long long pk2(float x, float y) {
    unsigned long long r; asm("mov.b64 %0, {%1, %2};" : "=l"(r) : "f"(x), "f"(y)); return r;
}
__device__ __forceinline__ float2 upk2(unsigned long long v) {
    float2 f; asm("mov.b64 {%0, %1}, %2;" : "=f"(f.x), "=f"(f.y) : "l"(v)); return f;
}
// tanh(x) = 1 - 2/(e^{2x}+1); saturates correctly at +-inf, ~1e-6 rel err
__device__ __forceinline__ float tanh_f(float x) {
    float e = __expf(2.0f * x);
    return 1.0f - __fdividef(2.0f, e + 1.0f);
}
__device__ __forceinline__ float sigm_f(float x) {
    float e = __expf(-x);
    return __fdividef(1.0f, 1.0f + e);
}

// ---------------- kernel 1: x-projection GEMM (tf32 wmma) ----------------
// P[b*S+t, col] = sum_k x[b,t,k] * W[k, col]   (bias folded into recurrent kernel)
__global__ __launch_bounds__(256) void xproj_kernel(const float* __restrict__ x,
                                                    const float* __restrict__ W) {
    int wid = threadIdx.x >> 5;
    int wm = wid & 3, wn = wid >> 2;                 // 4x2 warp layout
    int m0 = blockIdx.y * 128 + wm * 32;             // CTA tile: 128(M) x 64(N)
    int n0 = blockIdx.x * 64 + wn * 32;

    wmma::fragment<wmma::accumulator, 16, 16, 8, float> acc[2][2];
#pragma unroll
    for (int i = 0; i < 2; i++)
#pragma unroll
        for (int jj = 0; jj < 2; jj++) wmma::fill_fragment(acc[i][jj], 0.0f);

#pragma unroll 4
    for (int k = 0; k < Ii; k += 8) {
        wmma::fragment<wmma::matrix_a, 16, 16, 8, wmma::precision::tf32, wmma::row_major> a[2];
        wmma::fragment<wmma::matrix_b, 16, 16, 8, wmma::precision::tf32, wmma::row_major> b[2];
#pragma unroll
        for (int i = 0; i < 2; i++) {
            wmma::load_matrix_sync(a[i], x + (size_t)(m0 + 16 * i) * Ii + k, Ii);
#pragma unroll
            for (int e = 0; e < a[i].num_elements; e++) a[i].x[e] = wmma::__float_to_tf32(a[i].x[e]);
        }
#pragma unroll
        for (int jj = 0; jj < 2; jj++) {
            wmma::load_matrix_sync(b[jj], W + (size_t)k * G4 + n0 + 16 * jj, G4);
#pragma unroll
            for (int e = 0; e < b[jj].num_elements; e++) b[jj].x[e] = wmma::__float_to_tf32(b[jj].x[e]);
        }
#pragma unroll
        for (int i = 0; i < 2; i++)
#pragma unroll
            for (int jj = 0; jj < 2; jj++) wmma::mma_sync(acc[i][jj], a[i], b[jj], acc[i][jj]);
    }
#pragma unroll
    for (int i = 0; i < 2; i++)
#pragma unroll
        for (int jj = 0; jj < 2; jj++)
            wmma::store_matrix_sync(g_P + (size_t)(m0 + 16 * i) * G4 + n0 + 16 * jj,
                                    acc[i][jj], G4, wmma::mem_row_major);
}

// ---------------- kernel 2: recurrent chain ----------------
// 16 clusters x 8 CTAs. Each cluster owns 2 batch rows; each CTA owns 32 h-cols
// (-> 128 z-cols across the 4 gates) with its W_h slice held in REGISTERS.
// h is exchanged each step via DSMEM stores + one cluster barrier (double-buffered).
__global__ void __cluster_dims__(8, 1, 1) __launch_bounds__(512, 1)
lstm_rec(const float* __restrict__ W, const float* __restrict__ bias,
         const float* __restrict__ h0, const float* __restrict__ c0,
         float* __restrict__ out) {
    __shared__ __align__(16) float h_sm[2 * 2 * Hh];  // [parity][batch][256]
    __shared__ float zbuf[2 * 128];                   // [batch][local z col]

    const int tid = threadIdx.x;
    uint32_t rk; asm("mov.u32 %0, %%cluster_ctarank;" : "=r"(rk));
    const int cid = blockIdx.x >> 3;
    const int b0 = cid * 2;
    const int lc = tid >> 2;          // 0..127 local z column
    const int rg = tid & 3;           // row-group (4-way K split)
    const int q = lc >> 5, j = lc & 31;
    const int gcol = q * 256 + (int)rk * 32 + j;   // global z column

    // W_h slice -> registers: rows 16m+4rg+{0..3}, m=0..15 (64 rows/thread, packed pairs)
    unsigned long long w[32];
#pragma unroll
    for (int m = 0; m < 16; m++) {
        int r = 256 + 16 * m + 4 * rg;
        w[2 * m]     = pk2(W[(size_t)r * G4 + gcol],       W[(size_t)(r + 1) * G4 + gcol]);
        w[2 * m + 1] = pk2(W[(size_t)(r + 2) * G4 + gcol], W[(size_t)(r + 3) * G4 + gcol]);
    }
    const float bv = bias[gcol];

    // init h buffer 0 (each CTA loads full h0 for its 2 batches)
    {
        int b = tid >> 8, r = tid & 255;
        h_sm[b * Hh + r] = h0[(size_t)(b0 + b) * Hh + r];
    }
    // gate threads (tid<64) own c for (batch gb, h-col hc)
    const int gb = tid >> 5, gj = tid & 31;
    const int hc = (int)rk * 32 + gj;
    float creg = 0.0f;
    if (tid < 64) creg = c0[(size_t)(b0 + gb) * Hh + hc];

    const uint32_t hbase = (uint32_t)__cvta_generic_to_shared(h_sm);

    float pc0 = 0.f, pc1 = 0.f, pf0 = 0.f, pf1 = 0.f;
    if (rg == 0) {
        pc0 = g_P[((size_t)b0 * Ss) * G4 + gcol];
        pc1 = g_P[((size_t)(b0 + 1) * Ss) * G4 + gcol];
    }
    __syncthreads();

    int par = 0;
    for (int t = 0; t < Ss; t++) {
        // prefetch next step's x-projection (hidden behind matvec)
        if (rg == 0) {
            int tn = (t + 1 < Ss) ? t + 1 : t;
            pf0 = g_P[((size_t)b0 * Ss + tn) * G4 + gcol];
            pf1 = g_P[((size_t)(b0 + 1) * Ss + tn) * G4 + gcol];
        }
        // --- matvec: z_pre[b][gcol] += h[b][r] * W_h[r][gcol], packed f32x2 ---
        unsigned long long a0 = 0ull, a1 = 0ull, a2 = 0ull, a3 = 0ull;
        const ulonglong2* hp0 = (const ulonglong2*)(h_sm + par * 2 * Hh);
        const ulonglong2* hp1 = hp0 + (Hh / 4);
#pragma unroll
        for (int m = 0; m < 16; m++) {
            ulonglong2 v0 = hp0[4 * m + rg];
            ffma2(a0, w[2 * m], v0.x);
            ffma2(a1, w[2 * m + 1], v0.y);
            ulonglong2 v1 = hp1[4 * m + rg];
            ffma2(a2, w[2 * m], v1.x);
            ffma2(a3, w[2 * m + 1], v1.y);
        }
        float2 f0 = upk2(a0), f1 = upk2(a1), f2 = upk2(a2), f3 = upk2(a3);
        float s0 = (f0.x + f0.y) + (f1.x + f1.y);
        float s1 = (f2.x + f2.y) + (f3.x + f3.y);
        s0 += __shfl_xor_sync(0xffffffffu, s0, 1);
        s0 += __shfl_xor_sync(0xffffffffu, s0, 2);
        s1 += __shfl_xor_sync(0xffffffffu, s1, 1);
        s1 += __shfl_xor_sync(0xffffffffu, s1, 2);
        if (rg == 0) {   // one leader per z-column: z = tanh(hW + xW + b)
            zbuf[lc]       = tanh_f(s0 + pc0 + bv);
            zbuf[128 + lc] = tanh_f(s1 + pc1 + bv);
            pc0 = pf0; pc1 = pf1;
        }
        __syncthreads();
        if (tid < 64) {  // gate combine for (gb, hc)
            float zi = zbuf[gb * 128 + gj];
            float zf = zbuf[gb * 128 + 32 + gj];
            float zg = zbuf[gb * 128 + 64 + gj];
            float zo = zbuf[gb * 128 + 96 + gj];
            float ig = sigm_f(zi);
            float fg = sigm_f(zf);
            float gg = tanh_f(zg);
            float og = sigm_f(zo);
            creg = fg * creg + ig * gg;
            float hnew = tanh_f(creg) * og;
            out[((size_t)(b0 + gb) * Ss + t) * Hh + hc] = hnew;
            // broadcast h_new to all 8 CTAs' next-parity h buffer
            uint32_t laddr = hbase + (uint32_t)((((par ^ 1) * 2 + gb) * Hh + hc) * 4);
#pragma unroll
            for (int rr = 0; rr < 8; rr++) {
                uint32_t ra;
                asm volatile("mapa.shared::cluster.u32 %0, %1, %2;" : "=r"(ra) : "r"(laddr), "r"(rr));
                asm volatile("st.shared::cluster.f32 [%0], %1;" :: "r"(ra), "f"(hnew) : "memory");
            }
        }
        // one cluster barrier per step: orders DSMEM stores (release/acquire)
        asm volatile("barrier.cluster.arrive.aligned;" ::: "memory");
        asm volatile("barrier.cluster.wait.aligned;" ::: "memory");
        par ^= 1;
    }
}

// ---------------- kernel 3: zero the two trailing (1,B,H) outputs ----------------
__global__ void zero_tail(float* out, int total, int start) {
    int i = blockIdx.x * blockDim.x + threadIdx.x + start;
    if (i < total) out[i] = 0.0f;
}

extern "C" void kernel_launch(void* const* d_in, const int* in_sizes, int n_in,
                              void* d_out, int out_size) {
    const float* x    = (const float*)d_in[0];
    const float* h0   = (const float*)d_in[1];
    const float* c0   = (const float*)d_in[2];
    const float* W    = (const float*)d_in[3];
    const float* bias = (const float*)d_in[4];
    float* out = (float*)d_out;

    dim3 gx(G4 / 64, (Bb * Ss) / 128);
    xproj_kernel<<<gx, 256>>>(x, W);
    lstm_rec<<<128, 512>>>(W, bias, h0, c0, out);

    int main_elems = Bb * Ss * Hh;
    int tail = out_size - main_elems;
    if (tail > 0) zero_tail<<<(tail + 255) / 256, 256>>>(out, out_size, main_elems);
}

// round 5
// speedup vs baseline: 1.0361x; 1.0361x over previous
#include <cuda_runtime.h>
#include <mma.h>
#include <cstdint>
#include <cstddef>

using namespace nvcuda;

#define Bb 32
#define Ss 2048
#define Ii 256
#define Hh 256
#define G4 1024   // 4*H

// 256 MB scratch for the x-projection (device global: the sanctioned no-alloc path)
__device__ __align__(16) float g_P[(size_t)Bb * Ss * G4];

// ---------------- helpers ----------------
__device__ __forceinline__ void ffma2(unsigned long long &d, unsigned long long a, unsigned long long b) {
    asm volatile("fma.rn.f32x2 %0, %1, %2, %0;" : "+l"(d) : "l"(a), "l"(b));
}
__device__ __forceinline__ unsigned long long pk2(float x, float y) {
    unsigned long long r; asm("mov.b64 %0, {%1, %2};" : "=l"(r) : "f"(x), "f"(y)); return r;
}
__device__ __forceinline__ float2 upk2(unsigned long long v) {
    float2 f; asm("mov.b64 {%0, %1}, %2;" : "=f"(f.x), "=f"(f.y) : "l"(v)); return f;
}
// tanh(x) = 1 - 2/(e^{2x}+1); saturates correctly at +-inf, ~1e-6 rel err
__device__ __forceinline__ float tanh_f(float x) {
    float e = __expf(2.0f * x);
    return 1.0f - __fdividef(2.0f, e + 1.0f);
}
__device__ __forceinline__ float sigm_f(float x) {
    float e = __expf(-x);
    return __fdividef(1.0f, 1.0f + e);
}

// ---------------- kernel 1: x-projection GEMM (tf32 wmma) ----------------
// P[b*S+t, col] = sum_k x[b,t,k] * W[k, col]   (bias folded into recurrent kernel)
__global__ __launch_bounds__(256) void xproj_kernel(const float* __restrict__ x,
                                                    const float* __restrict__ W) {
    int wid = threadIdx.x >> 5;
    int wm = wid & 3, wn = wid >> 2;                 // 4x2 warp layout
    int m0 = blockIdx.y * 128 + wm * 32;             // CTA tile: 128(M) x 64(N)
    int n0 = blockIdx.x * 64 + wn * 32;

    wmma::fragment<wmma::accumulator, 16, 16, 8, float> acc[2][2];
#pragma unroll
    for (int i = 0; i < 2; i++)
#pragma unroll
        for (int jj = 0; jj < 2; jj++) wmma::fill_fragment(acc[i][jj], 0.0f);

#pragma unroll 4
    for (int k = 0; k < Ii; k += 8) {
        wmma::fragment<wmma::matrix_a, 16, 16, 8, wmma::precision::tf32, wmma::row_major> a[2];
        wmma::fragment<wmma::matrix_b, 16, 16, 8, wmma::precision::tf32, wmma::row_major> b[2];
#pragma unroll
        for (int i = 0; i < 2; i++) {
            wmma::load_matrix_sync(a[i], x + (size_t)(m0 + 16 * i) * Ii + k, Ii);
#pragma unroll
            for (int e = 0; e < a[i].num_elements; e++) a[i].x[e] = wmma::__float_to_tf32(a[i].x[e]);
        }
#pragma unroll
        for (int jj = 0; jj < 2; jj++) {
            wmma::load_matrix_sync(b[jj], W + (size_t)k * G4 + n0 + 16 * jj, G4);
#pragma unroll
            for (int e = 0; e < b[jj].num_elements; e++) b[jj].x[e] = wmma::__float_to_tf32(b[jj].x[e]);
        }
#pragma unroll
        for (int i = 0; i < 2; i++)
#pragma unroll
            for (int jj = 0; jj < 2; jj++) wmma::mma_sync(acc[i][jj], a[i], b[jj], acc[i][jj]);
    }
#pragma unroll
    for (int i = 0; i < 2; i++)
#pragma unroll
        for (int jj = 0; jj < 2; jj++)
            wmma::store_matrix_sync(g_P + (size_t)(m0 + 16 * i) * G4 + n0 + 16 * jj,
                                    acc[i][jj], G4, wmma::mem_row_major);
}

// ---------------- kernel 2: recurrent chain ----------------
// 16 clusters x 8 CTAs. Each cluster owns 2 batch rows; each CTA owns 32 h-cols
// (-> 128 z-cols across the 4 gates) with its W_h slice held in REGISTERS.
// h is exchanged each step via DSMEM stores + one cluster barrier (double-buffered).
__global__ void __cluster_dims__(8, 1, 1) __launch_bounds__(512, 1)
lstm_rec(const float* __restrict__ W, const float* __restrict__ bias,
         const float* __restrict__ h0, const float* __restrict__ c0,
         float* __restrict__ out) {
    __shared__ __align__(16) float h_sm[2 * 2 * Hh];  // [parity][batch][256]
    __shared__ float zbuf[2 * 128];                   // [batch][local z col]

    const int tid = threadIdx.x;
    uint32_t rk; asm("mov.u32 %0, %%cluster_ctarank;" : "=r"(rk));
    const int cid = blockIdx.x >> 3;
    const int b0 = cid * 2;
    const int lc = tid >> 2;          // 0..127 local z column
    const int rg = tid & 3;           // row-group (4-way K split)
    const int q = lc >> 5, j = lc & 31;
    const int gcol = q * 256 + (int)rk * 32 + j;   // global z column

    // W_h slice -> registers: rows 16m+4rg+{0..3}, m=0..15 (64 rows/thread, packed pairs)
    unsigned long long w[32];
#pragma unroll
    for (int m = 0; m < 16; m++) {
        int r = 256 + 16 * m + 4 * rg;
        w[2 * m]     = pk2(W[(size_t)r * G4 + gcol],       W[(size_t)(r + 1) * G4 + gcol]);
        w[2 * m + 1] = pk2(W[(size_t)(r + 2) * G4 + gcol], W[(size_t)(r + 3) * G4 + gcol]);
    }
    const float bv = bias[gcol];

    // init h buffer 0 (each CTA loads full h0 for its 2 batches)
    {
        int b = tid >> 8, r = tid & 255;
        h_sm[b * Hh + r] = h0[(size_t)(b0 + b) * Hh + r];
    }
    // gate threads (tid<64) own c for (batch gb, h-col hc)
    const int gb = tid >> 5, gj = tid & 31;
    const int hc = (int)rk * 32 + gj;
    float creg = 0.0f;
    if (tid < 64) creg = c0[(size_t)(b0 + gb) * Hh + hc];

    const uint32_t hbase = (uint32_t)__cvta_generic_to_shared(h_sm);

    float pc0 = 0.f, pc1 = 0.f, pf0 = 0.f, pf1 = 0.f;
    if (rg == 0) {
        pc0 = g_P[((size_t)b0 * Ss) * G4 + gcol];
        pc1 = g_P[((size_t)(b0 + 1) * Ss) * G4 + gcol];
    }
    __syncthreads();

    int par = 0;
    for (int t = 0; t < Ss; t++) {
        // prefetch next step's x-projection (hidden behind matvec)
        if (rg == 0) {
            int tn = (t + 1 < Ss) ? t + 1 : t;
            pf0 = g_P[((size_t)b0 * Ss + tn) * G4 + gcol];
            pf1 = g_P[((size_t)(b0 + 1) * Ss + tn) * G4 + gcol];
        }
        // --- matvec: z_pre[b][gcol] += h[b][r] * W_h[r][gcol], packed f32x2 ---
        unsigned long long a0 = 0ull, a1 = 0ull, a2 = 0ull, a3 = 0ull;
        const ulonglong2* hp0 = (const ulonglong2*)(h_sm + par * 2 * Hh);
        const ulonglong2* hp1 = hp0 + (Hh / 4);
#pragma unroll
        for (int m = 0; m < 16; m++) {
            ulonglong2 v0 = hp0[4 * m + rg];
            ffma2(a0, w[2 * m], v0.x);
            ffma2(a1, w[2 * m + 1], v0.y);
            ulonglong2 v1 = hp1[4 * m + rg];
            ffma2(a2, w[2 * m], v1.x);
            ffma2(a3, w[2 * m + 1], v1.y);
        }
        float2 f0 = upk2(a0), f1 = upk2(a1), f2 = upk2(a2), f3 = upk2(a3);
        float s0 = (f0.x + f0.y) + (f1.x + f1.y);
        float s1 = (f2.x + f2.y) + (f3.x + f3.y);
        s0 += __shfl_xor_sync(0xffffffffu, s0, 1);
        s0 += __shfl_xor_sync(0xffffffffu, s0, 2);
        s1 += __shfl_xor_sync(0xffffffffu, s1, 1);
        s1 += __shfl_xor_sync(0xffffffffu, s1, 2);
        if (rg == 0) {   // one leader per z-column: z = tanh(hW + xW + b)
            zbuf[lc]       = tanh_f(s0 + pc0 + bv);
            zbuf[128 + lc] = tanh_f(s1 + pc1 + bv);
            pc0 = pf0; pc1 = pf1;
        }
        __syncthreads();
        if (tid < 64) {  // gate combine for (gb, hc)
            float zi = zbuf[gb * 128 + gj];
            float zf = zbuf[gb * 128 + 32 + gj];
            float zg = zbuf[gb * 128 + 64 + gj];
            float zo = zbuf[gb * 128 + 96 + gj];
            float ig = sigm_f(zi);
            float fg = sigm_f(zf);
            float gg = tanh_f(zg);
            float og = sigm_f(zo);
            creg = fg * creg + ig * gg;
            float hnew = tanh_f(creg) * og;
            out[((size_t)(b0 + gb) * Ss + t) * Hh + hc] = hnew;
            // broadcast h_new to all 8 CTAs' next-parity h buffer
            uint32_t laddr = hbase + (uint32_t)((((par ^ 1) * 2 + gb) * Hh + hc) * 4);
#pragma unroll
            for (int rr = 0; rr < 8; rr++) {
                uint32_t ra;
                asm volatile("mapa.shared::cluster.u32 %0, %1, %2;" : "=r"(ra) : "r"(laddr), "r"(rr));
                asm volatile("st.shared::cluster.f32 [%0], %1;" :: "r"(ra), "f"(hnew) : "memory");
            }
        }
        // one cluster barrier per step: orders DSMEM stores (release/acquire)
        asm volatile("barrier.cluster.arrive.aligned;" ::: "memory");
        asm volatile("barrier.cluster.wait.aligned;" ::: "memory");
        par ^= 1;
    }
}

// ---------------- kernel 3: zero the two trailing (1,B,H) outputs ----------------
__global__ void zero_tail(float* out, int total, int start) {
    int i = blockIdx.x * blockDim.x + threadIdx.x + start;
    if (i < total) out[i] = 0.0f;
}

extern "C" void kernel_launch(void* const* d_in, const int* in_sizes, int n_in,
                              void* d_out, int out_size) {
    const float* x    = (const float*)d_in[0];
    const float* h0   = (const float*)d_in[1];
    const float* c0   = (const float*)d_in[2];
    const float* W    = (const float*)d_in[3];
    const float* bias = (const float*)d_in[4];
    float* out = (float*)d_out;

    dim3 gx(G4 / 64, (Bb * Ss) / 128);
    xproj_kernel<<<gx, 256>>>(x, W);
    lstm_rec<<<128, 512>>>(W, bias, h0, c0, out);

    int main_elems = Bb * Ss * Hh;
    int tail = out_size - main_elems;
    if (tail > 0) zero_tail<<<(tail + 255) / 256, 256>>>(out, out_size, main_elems);
}